// round 10
// baseline (speedup 1.0000x reference)
#include <cuda_runtime.h>
#include <cuda_fp16.h>
#include <cstdint>
#include <cfloat>

#define Dd 64
#define Kk 1024
#define TR 64
#define NCH 8
#define NTILES 1024
#define GRID 444

#define BPITCH 144
#define SMB_BUFSZ (128*BPITCH)

// ---------------- smem layout (bytes) ----------------
#define SM_B    0                  // 2 x 18432 = 36864
#define SM_XS   36864              // 64 x 65 fp32 -> 53504
#define SM_CN   53504              // -> 57600
#define SM_XN   57600              // -> 57856
#define SM_TAU  57856              // -> 58112
#define SM_HM   58112              // halfmin [2][64][8] -> 62208
#define SM_RVH  62208              // -> 62720
#define SM_RIH  62720              // -> 63232
#define SM_RV2H 63232              // -> 63744
#define SM_BI   63744              // -> 64000
#define SM_RES  64000              // 64 x u64 -> 64512
#define SM_ITM  64512              // 512 int -> 66560
#define SM_FLG  66560              // -> 66816
#define SM_CNT  66816              // 8
#define SM_RS   66824              // -> 67848
#define SM_TOTAL 67848

// ---------------- scratch ----------------
__device__ float  g_codebookT[Kk*Dd];
__device__ float  g_cnorm[Kk];
__device__ __half g_Bh16[Kk*Dd];
__device__ int    g_nm_i;
__device__ int    g_nml_i;
__device__ float  g_blocksum[NTILES];
__device__ int    g_done;
__device__ int    g_tile;

// ---------------- helpers ----------------
__device__ __forceinline__ uint32_t smem_u32(const void* p){
    uint32_t a; asm("{ .reg .u64 t; cvta.to.shared.u64 t, %1; cvt.u32.u64 %0, t; }" : "=r"(a) : "l"(p)); return a;
}
__device__ __forceinline__ uint4 lds128(uint32_t a){
    uint4 v; asm volatile("ld.shared.v4.u32 {%0,%1,%2,%3}, [%4];"
        : "=r"(v.x),"=r"(v.y),"=r"(v.z),"=r"(v.w) : "r"(a)); return v;
}
#define CP16(dst, src) asm volatile("cp.async.cg.shared.global [%0], [%1], 16;" :: "r"(dst), "l"(src) : "memory")
#define CP_COMMIT()    asm volatile("cp.async.commit_group;" ::: "memory")
#define CP_WAIT(n)     asm volatile("cp.async.wait_group %0;" :: "n"(n) : "memory")

#define MMA16(c0,c1,c2,c3, a0,a1,a2,a3, b0,b1) \
  asm volatile("mma.sync.aligned.m16n8k16.row.col.f32.f16.f16.f32 " \
    "{%0,%1,%2,%3},{%4,%5,%6,%7},{%8,%9},{%0,%1,%2,%3};" \
    : "+f"(c0),"+f"(c1),"+f"(c2),"+f"(c3) \
    : "r"(a0),"r"(a1),"r"(a2),"r"(a3),"r"(b0),"r"(b1))

#define UPD(bv,bi,bv2, s, idx) do{ float _s=(s); \
    if (_s < (bv)){ (bv2)=(bv); (bv)=_s; (bi)=(idx); } \
    else if (_s < (bv2)) (bv2)=_s; }while(0)

__device__ __forceinline__ int bslot(int d){
    int s = d >> 4, r = d & 15;
    return ((r >> 1) & 3) * 16 + s * 4 + ((r >> 3) & 1) * 2 + (r & 1);
}

__device__ __forceinline__ unsigned long long packsi(float s, int idx){
    uint32_t u = __float_as_uint(s);
    u = (u >> 31) ? ~u : (u | 0x80000000u);
    return ((unsigned long long)u << 10) | (uint32_t)idx;
}

// ---------------------------------------------------------------------------
// Prep: transpose, fp16 hi split (permuted), norms; resets work-queue/done.
// ---------------------------------------------------------------------------
__global__ void vq_prep(const float* __restrict__ cm){
    __shared__ float tile[64][17];
    __shared__ float mx_s[16], mxl_s[16];
    const int t  = threadIdx.x;
    const int kb = blockIdx.x * 16;
    if (blockIdx.x == 0 && t == 0){ g_done = 0; g_tile = 0; }
#pragma unroll
    for (int i = 0; i < 4; ++i){
        int e = t + 256*i;
        int d = e >> 4, j = e & 15;
        tile[d][j] = cm[d*Kk + kb + j];
    }
    __syncthreads();
#pragma unroll
    for (int i = 0; i < 4; ++i){
        int e = t + 256*i;
        int kr = e >> 6, j = e & 63;
        float v = tile[j][kr];
        g_codebookT[(kb + kr)*Dd + j] = v;
        g_Bh16[(kb + kr)*Dd + bslot(j)] = __float2half_rn(v);
    }
    if (t < 16){
        float s = 0.f, sl = 0.f;
#pragma unroll
        for (int d = 0; d < 64; ++d){
            float v = tile[d][t];
            float l = v - __half2float(__float2half_rn(v));
            s += v*v; sl += l*l;
        }
        g_cnorm[kb + t] = s;
        mx_s[t] = s; mxl_s[t] = sl;
    }
    __syncthreads();
    if (t == 0){
        float m = mx_s[0], ml = mxl_s[0];
#pragma unroll
        for (int i = 1; i < 16; ++i){ m = fmaxf(m, mx_s[i]); ml = fmaxf(ml, mxl_s[i]); }
        atomicMax(&g_nm_i,  __float_as_int(m));
        atomicMax(&g_nml_i, __float_as_int(ml));
    }
}

// ---------------------------------------------------------------------------
// Main: persistent CTAs, dynamic tile queue. Per tile: fp32-acc fp16 screen +
// rigorous tau + chunk-granular exact refine + gather/STE/loss.
// ---------------------------------------------------------------------------
__global__ __launch_bounds__(256, 3)
void vq_main(const float* __restrict__ x, const float* __restrict__ cm,
             float* __restrict__ out, float* __restrict__ out_idx,
             float* __restrict__ out_loss)
{
    extern __shared__ char smem[];
    __shared__ int s_tile;
    __shared__ int s_done;
    const uint32_t sb = smem_u32(smem);
    float* Xs    = (float*)(smem + SM_XS);
    float* cn_s  = (float*)(smem + SM_CN);
    float* xn_s  = (float*)(smem + SM_XN);
    float* tau_s = (float*)(smem + SM_TAU);
    float* hm_s  = (float*)(smem + SM_HM);
    float* RVh   = (float*)(smem + SM_RVH);
    int*   RIh   = (int*)  (smem + SM_RIH);
    float* RV2h  = (float*)(smem + SM_RV2H);
    int*   besti_s = (int*)(smem + SM_BI);
    unsigned long long* res_s = (unsigned long long*)(smem + SM_RES);
    int*   items = (int*)  (smem + SM_ITM);
    int*   flg_s = (int*)  (smem + SM_FLG);
    int*   nit_p = (int*)  (smem + SM_CNT);
    float* RS    = (float*)(smem + SM_RS);

    const int tid = threadIdx.x;
    const int wid = tid >> 5, lid = tid & 31;
    const int l4  = lid & 3,  gq  = lid >> 2;
    const int colhalf = (wid >> 2) & 1;
    const int rq = wid & 3;
    const int r0 = rq*16 + gq, r1 = r0 + 8;

    // ---- tile-invariant setup ----
#pragma unroll
    for (int i = 0; i < 4; ++i) cn_s[tid + 256*i] = g_cnorm[tid + 256*i];
    const float nm  = sqrtf(__int_as_float(g_nm_i));
    const float nml = sqrtf(__int_as_float(g_nml_i));

    // cp.async address bases (tile-invariant)
    uint64_t srcbase; asm("cvta.to.global.u64 %0, %1;" : "=l"(srcbase)
                          : "l"(g_Bh16 + (size_t)(tid >> 3)*Dd + (tid & 7)*8));
    const uint32_t dstbase = sb + SM_B + (uint32_t)((tid >> 3)*BPITCH + (tid & 7)*16);

    for (;;){
        if (tid == 0) s_tile = atomicAdd(&g_tile, 1);
        __syncthreads();                    // also fences prior tile's smem use
        const int tile = s_tile;
        if (tile >= NTILES) break;
        const int row0 = tile * TR;
        if (tid == 0) *nit_p = 0;

        // ---- cp.async B chunk 0 -> buf0 ----
#pragma unroll
        for (int i = 0; i < 4; ++i)
            CP16(dstbase + (uint32_t)(i*32*BPITCH), srcbase + (uint64_t)(i*32*128));
        CP_COMMIT();

        // ---- X tile -> Xs ----
        {
            const float4* x4 = (const float4*)(x + (size_t)row0 * Dd);
#pragma unroll
            for (int i = 0; i < 4; ++i){
                int e = tid + 256*i;
                int r = e >> 4, g = e & 15;
                float4 v = x4[e];
                Xs[r*65 + g*4 + 0] = v.x; Xs[r*65 + g*4 + 1] = v.y;
                Xs[r*65 + g*4 + 2] = v.z; Xs[r*65 + g*4 + 3] = v.w;
            }
        }
        __syncthreads();

        // ---- per-row norms + rigorous tau ----
        if (tid < 64){
            float s = 0.f, sl = 0.f;
#pragma unroll
            for (int d = 0; d < 64; ++d){
                float v = Xs[tid*65 + d];
                float l = v - __half2float(__float2half_rn(v));
                s += v*v; sl += l*l;
            }
            xn_s[tid] = s;
            float xl = sqrtf(sl), xf = sqrtf(s);
            float tdot = xl*nm + (xf + xl)*nml;
            tau_s[tid] = 4.0f*tdot + 1e-3f;
        }

        // ---- A fragments: fp16 hi ----
        uint32_t Ah[16];
#pragma unroll
        for (int s = 0; s < 4; ++s){
#pragma unroll
            for (int p = 0; p < 2; ++p){
                int k0 = 16*s + 2*l4 + 8*p;
                __half2 hh;
                hh = __halves2half2(__float2half_rn(Xs[r0*65 + k0]),
                                    __float2half_rn(Xs[r0*65 + k0 + 1]));
                Ah[s*4 + p*2 + 0] = *(uint32_t*)&hh;
                hh = __halves2half2(__float2half_rn(Xs[r1*65 + k0]),
                                    __float2half_rn(Xs[r1*65 + k0 + 1]));
                Ah[s*4 + p*2 + 1] = *(uint32_t*)&hh;
            }
        }

        float bv0 = FLT_MAX, bv20 = FLT_MAX, bv1 = FLT_MAX, bv21 = FLT_MAX;
        int   bi0 = 0, bi1 = 0;

        // ---- chunk loop ----
        for (int c = 0; c < NCH; ++c){
            CP_WAIT(0);
            __syncthreads();
            if (c + 1 < NCH){
                const uint32_t dstb = dstbase + (uint32_t)(((c + 1) & 1) * SMB_BUFSZ);
                const uint64_t srcb = srcbase + (uint64_t)((c + 1) * 16384);
#pragma unroll
                for (int i = 0; i < 4; ++i)
                    CP16(dstb + (uint32_t)(i*32*BPITCH), srcb + (uint64_t)(i*32*128));
                CP_COMMIT();
            }

            const uint32_t bbase = sb + SM_B + (uint32_t)(c & 1) * SMB_BUFSZ
                                 + (uint32_t)((colhalf*64 + gq) * BPITCH + l4 * 32);
            float cmin0 = FLT_MAX, cmin1 = FLT_MAX;
#pragma unroll
            for (int nt = 0; nt < 8; ++nt){
                const uint32_t nb = bbase + (uint32_t)(nt * 8 * BPITCH);
                uint4 b0 = lds128(nb);
                uint4 b1 = lds128(nb + 16);

                float c0=0.f, c1=0.f, c2=0.f, c3=0.f;
                MMA16(c0,c1,c2,c3, Ah[0], Ah[1], Ah[2], Ah[3],  b0.x, b0.y);
                MMA16(c0,c1,c2,c3, Ah[4], Ah[5], Ah[6], Ah[7],  b0.z, b0.w);
                MMA16(c0,c1,c2,c3, Ah[8], Ah[9], Ah[10],Ah[11], b1.x, b1.y);
                MMA16(c0,c1,c2,c3, Ah[12],Ah[13],Ah[14],Ah[15], b1.z, b1.w);

                const int colb = c*128 + colhalf*64 + nt*8 + l4*2;
                const float2 cn2 = *(const float2*)&cn_s[colb];
                float s0 = fmaf(-2.f, c0, cn2.x);
                float s1 = fmaf(-2.f, c1, cn2.y);
                float s2 = fmaf(-2.f, c2, cn2.x);
                float s3 = fmaf(-2.f, c3, cn2.y);
                UPD(bv0, bi0, bv20, s0, colb);
                UPD(bv0, bi0, bv20, s1, colb + 1);
                UPD(bv1, bi1, bv21, s2, colb);
                UPD(bv1, bi1, bv21, s3, colb + 1);
                cmin0 = fminf(cmin0, fminf(s0, s1));
                cmin1 = fminf(cmin1, fminf(s2, s3));
            }
            cmin0 = fminf(cmin0, __shfl_xor_sync(~0u, cmin0, 1));
            cmin0 = fminf(cmin0, __shfl_xor_sync(~0u, cmin0, 2));
            cmin1 = fminf(cmin1, __shfl_xor_sync(~0u, cmin1, 1));
            cmin1 = fminf(cmin1, __shfl_xor_sync(~0u, cmin1, 2));
            if (l4 == 0){
                hm_s[(colhalf*64 + r0)*8 + c] = cmin0;
                hm_s[(colhalf*64 + r1)*8 + c] = cmin1;
            }
        }

        // ---- quad-reduce best/second ----
#pragma unroll
        for (int off = 1; off < 4; off <<= 1){
            float ov  = __shfl_xor_sync(~0u, bv0, off);
            int   oi  = __shfl_xor_sync(~0u, bi0, off);
            float ov2 = __shfl_xor_sync(~0u, bv20, off);
            float lose;
            if (ov < bv0 || (ov == bv0 && oi < bi0)){ lose = bv0; bv0 = ov; bi0 = oi; }
            else lose = ov;
            bv20 = fminf(bv20, fminf(ov2, lose));

            ov  = __shfl_xor_sync(~0u, bv1, off);
            oi  = __shfl_xor_sync(~0u, bi1, off);
            ov2 = __shfl_xor_sync(~0u, bv21, off);
            if (ov < bv1 || (ov == bv1 && oi < bi1)){ lose = bv1; bv1 = ov; bi1 = oi; }
            else lose = ov;
            bv21 = fminf(bv21, fminf(ov2, lose));
        }
        if (l4 == 0){
            RVh [colhalf*64 + r0] = bv0;  RIh[colhalf*64 + r0] = bi0;  RV2h[colhalf*64 + r0] = bv20;
            RVh [colhalf*64 + r1] = bv1;  RIh[colhalf*64 + r1] = bi1;  RV2h[colhalf*64 + r1] = bv21;
        }
        __syncthreads();

        // ---- merge halves, flag, build (row,chunk) items ----
        if (tid < 64){
            float v0 = RVh[tid],  v1 = RVh[64+tid];
            int   i0 = RIh[tid],  i1 = RIh[64+tid];
            float s0 = RV2h[tid], s1 = RV2h[64+tid];
            float bv; int bi; float sec;
            if (v1 < v0 || (v1 == v0 && i1 < i0)){ bv = v1; bi = i1; sec = fminf(v0, s1); }
            else                                  { bv = v0; bi = i0; sec = fminf(v1, s0); }
            besti_s[tid] = bi;
            const float tau = tau_s[tid];
            int fl = (sec - bv < tau) ? 1 : 0;
            flg_s[tid] = fl;
            if (fl){
                res_s[tid] = ~0ull;
                const float lim = bv + tau;
#pragma unroll
                for (int c = 0; c < 8; ++c){
                    float cmn = fminf(hm_s[tid*8 + c], hm_s[(64+tid)*8 + c]);
                    if (cmn <= lim){
                        int s = atomicAdd(nit_p, 1);
                        items[s] = (tid << 3) | c;
                    }
                }
            }
        }
        __syncthreads();

        // ---- chunk-granular exact refine: warp per item ----
        const int nitems = *nit_p;
        for (int it = wid; it < nitems; it += 8){
            const int item = items[it];
            const int row = item >> 3, ch = item & 7;
            float a0 = 0.f, a1 = 0.f, a2 = 0.f, a3 = 0.f;
            const float4* bp = (const float4*)(cm + ch*128) + lid;
#pragma unroll 16
            for (int d = 0; d < 64; ++d){
                float4 b = __ldg(bp + d*256);
                float xv = Xs[row*65 + d];
                a0 = fmaf(xv, b.x, a0);
                a1 = fmaf(xv, b.y, a1);
                a2 = fmaf(xv, b.z, a2);
                a3 = fmaf(xv, b.w, a3);
            }
            const float xnr = xn_s[row];
            const int k0 = ch*128 + lid*4;
            float best = (xnr - 2.0f*a0) + cn_s[k0];     int bidx = k0;
            float sv;
            sv = (xnr - 2.0f*a1) + cn_s[k0+1]; if (sv < best){ best = sv; bidx = k0+1; }
            sv = (xnr - 2.0f*a2) + cn_s[k0+2]; if (sv < best){ best = sv; bidx = k0+2; }
            sv = (xnr - 2.0f*a3) + cn_s[k0+3]; if (sv < best){ best = sv; bidx = k0+3; }
#pragma unroll
            for (int off = 16; off > 0; off >>= 1){
                float ov = __shfl_xor_sync(~0u, best, off);
                int   oi = __shfl_xor_sync(~0u, bidx, off);
                if (ov < best || (ov == best && oi < bidx)){ best = ov; bidx = oi; }
            }
            if (lid == 0) atomicMin(&res_s[row], packsi(best, bidx));
        }
        __syncthreads();
        if (tid < 64 && flg_s[tid])
            besti_s[tid] = (int)(res_s[tid] & 0x3FFull);
        __syncthreads();

        // ---- gather + STE output + loss ----
        float partial = 0.f;
        {
            const int row = tid >> 2, q = tid & 3;
            const int bi = besti_s[row];
            if (q == 0) out_idx[row0 + row] = (float)bi;
            const float4* q4 = (const float4*)(g_codebookT + (size_t)bi * Dd) + q*4;
            float4* o4 = (float4*)(out + (size_t)(row0 + row) * Dd) + q*4;
#pragma unroll
            for (int g = 0; g < 4; ++g){
                float4 qv = q4[g];
                int db = q*16 + g*4;
                float xa = Xs[row*65 + db + 0];
                float xb = Xs[row*65 + db + 1];
                float xc = Xs[row*65 + db + 2];
                float xd = Xs[row*65 + db + 3];
                float da = qv.x - xa, dbv = qv.y - xb, dc = qv.z - xc, dd = qv.w - xd;
                partial += da*da + dbv*dbv + dc*dc + dd*dd;
                float4 o; o.x = xa + da; o.y = xb + dbv; o.z = xc + dc; o.w = xd + dd;
                o4[g] = o;
            }
        }
        RS[tid] = partial;
        __syncthreads();
        for (int s = 128; s > 0; s >>= 1){
            if (tid < s) RS[tid] += RS[tid + s];
            __syncthreads();
        }
        if (tid == 0) g_blocksum[tile] = RS[0];
    }

    // ---- fused finish: last CTA does deterministic fp64 loss sum ----
    __threadfence();
    if (tid == 0) s_done = atomicAdd(&g_done, 1);
    __syncthreads();
    if (s_done == (int)gridDim.x - 1){
        __shared__ double part[32];
        if (tid < 32){
            double s = 0.0;
            const int per = NTILES / 32;
            for (int i = 0; i < per; ++i) s += (double)g_blocksum[tid*per + i];
            part[tid] = s;
        }
        __syncthreads();
        if (tid == 0){
            double tot = 0.0;
            for (int i = 0; i < 32; ++i) tot += part[i];
            float q_loss = (float)(tot / (double)(65536.0 * 64.0));
            out_loss[0] = q_loss + 0.25f * q_loss;
        }
    }
}

// ---------------------------------------------------------------------------
extern "C" void kernel_launch(void* const* d_in, const int* in_sizes, int n_in,
                              void* d_out, int out_size) {
    const float* x  = (const float*)d_in[0];
    const float* cm = (const float*)d_in[1];
    float* out = (float*)d_out;

    const int N = in_sizes[0] / Dd;            // 65536
    float* out_idx  = out + (size_t)N * Dd;
    float* out_loss = out_idx + N;

    cudaFuncSetAttribute(vq_main, cudaFuncAttributeMaxDynamicSharedMemorySize, SM_TOTAL);

    vq_prep<<<Kk/16, 256>>>(cm);
    vq_main<<<GRID, 256, SM_TOTAL>>>(x, cm, out, out_idx, out_loss);
}

// round 11
// speedup vs baseline: 1.0080x; 1.0080x over previous
#include <cuda_runtime.h>
#include <cuda_fp16.h>
#include <cstdint>
#include <cfloat>

#define Dd 64
#define Kk 1024
#define TR 64
#define NCH 8
#define NTILES 1024
#define GRID 296

#define BPITCH 144
#define SMB_BUFSZ (128*BPITCH)

// ---------------- smem layout (bytes) ----------------
#define SM_B    0                  // 2 x 18432 = 36864
#define SM_XS   36864              // 64 x 65 fp32 -> 53504
#define SM_CN   53504              // -> 57600
#define SM_XN   57600              // -> 57856
#define SM_TAU  57856              // -> 58112
#define SM_HM   58112              // halfmin [2][64][8] -> 62208
#define SM_RVH  62208              // -> 62720
#define SM_RIH  62720              // -> 63232
#define SM_RV2H 63232              // -> 63744
#define SM_BI   63744              // -> 64000
#define SM_RES  64000              // 64 x u64 -> 64512
#define SM_ITM  64512              // 512 int -> 66560
#define SM_FLG  66560              // -> 66816
#define SM_CNT  66816              // 8
#define SM_RS   66824              // -> 67848
#define SM_TOTAL 67848

// ---------------- scratch ----------------
__device__ float  g_codebookT[Kk*Dd];
__device__ float  g_cnorm[Kk];
__device__ __half g_Bh16[Kk*Dd];
__device__ int    g_nm_i;
__device__ int    g_nml_i;
__device__ float  g_blocksum[NTILES];
__device__ int    g_done;
__device__ int    g_tile;

// ---------------- helpers ----------------
__device__ __forceinline__ uint32_t smem_u32(const void* p){
    uint32_t a; asm("{ .reg .u64 t; cvta.to.shared.u64 t, %1; cvt.u32.u64 %0, t; }" : "=r"(a) : "l"(p)); return a;
}
__device__ __forceinline__ uint4 lds128(uint32_t a){
    uint4 v; asm volatile("ld.shared.v4.u32 {%0,%1,%2,%3}, [%4];"
        : "=r"(v.x),"=r"(v.y),"=r"(v.z),"=r"(v.w) : "r"(a)); return v;
}
#define CP16(dst, src) asm volatile("cp.async.cg.shared.global [%0], [%1], 16;" :: "r"(dst), "l"(src) : "memory")
#define CP_COMMIT()    asm volatile("cp.async.commit_group;" ::: "memory")
#define CP_WAIT(n)     asm volatile("cp.async.wait_group %0;" :: "n"(n) : "memory")

#define MMA16(c0,c1,c2,c3, a0,a1,a2,a3, b0,b1) \
  asm volatile("mma.sync.aligned.m16n8k16.row.col.f32.f16.f16.f32 " \
    "{%0,%1,%2,%3},{%4,%5,%6,%7},{%8,%9},{%0,%1,%2,%3};" \
    : "+f"(c0),"+f"(c1),"+f"(c2),"+f"(c3) \
    : "r"(a0),"r"(a1),"r"(a2),"r"(a3),"r"(b0),"r"(b1))

__device__ __forceinline__ int bslot(int d){
    int s = d >> 4, r = d & 15;
    return ((r >> 1) & 3) * 16 + s * 4 + ((r >> 3) & 1) * 2 + (r & 1);
}

__device__ __forceinline__ unsigned long long packsi(float s, int idx){
    uint32_t u = __float_as_uint(s);
    u = (u >> 31) ? ~u : (u | 0x80000000u);
    return ((unsigned long long)u << 10) | (uint32_t)idx;
}

// ---------------------------------------------------------------------------
// Prep: 128 blocks x 8 codes — transpose, fp16 hi split (permuted), norms.
// ---------------------------------------------------------------------------
__global__ void vq_prep(const float* __restrict__ cm){
    __shared__ float tile[64][9];
    __shared__ float mx_s[8], mxl_s[8];
    const int t  = threadIdx.x;          // 128 threads
    const int kb = blockIdx.x * 8;
    if (blockIdx.x == 0 && t == 0){ g_done = 0; g_tile = 0; }
#pragma unroll
    for (int i = 0; i < 4; ++i){
        int e = t + 128*i;               // 0..511
        int d = e >> 3, j = e & 7;
        tile[d][j] = cm[d*Kk + kb + j];
    }
    __syncthreads();
#pragma unroll
    for (int i = 0; i < 4; ++i){
        int e = t + 128*i;
        int kr = e >> 6, jd = e & 63;    // kr 0..7, jd dim
        float v = tile[jd][kr];
        g_codebookT[(kb + kr)*Dd + jd] = v;
        g_Bh16[(kb + kr)*Dd + bslot(jd)] = __float2half_rn(v);
    }
    if (t < 8){
        float s = 0.f, sl = 0.f;
#pragma unroll
        for (int d = 0; d < 64; ++d){
            float v = tile[d][t];
            float l = v - __half2float(__float2half_rn(v));
            s += v*v; sl += l*l;
        }
        g_cnorm[kb + t] = s;
        mx_s[t] = s; mxl_s[t] = sl;
    }
    __syncthreads();
    if (t == 0){
        float m = mx_s[0], ml = mxl_s[0];
#pragma unroll
        for (int i = 1; i < 8; ++i){ m = fmaxf(m, mx_s[i]); ml = fmaxf(ml, mxl_s[i]); }
        atomicMax(&g_nm_i,  __float_as_int(m));
        atomicMax(&g_nml_i, __float_as_int(ml));
    }
}

// ---------------------------------------------------------------------------
// Main: persistent CTAs; screen with split MMA chains + pair-min argmin
// bookkeeping; rigorous tau; chunk-granular exact refine; gather/STE/loss.
// ---------------------------------------------------------------------------
__global__ __launch_bounds__(256, 2)
void vq_main(const float* __restrict__ x, const float* __restrict__ cm,
             float* __restrict__ out, float* __restrict__ out_idx,
             float* __restrict__ out_loss)
{
    extern __shared__ char smem[];
    __shared__ int s_tile;
    __shared__ int s_done;
    const uint32_t sb = smem_u32(smem);
    float* Xs    = (float*)(smem + SM_XS);
    float* cn_s  = (float*)(smem + SM_CN);
    float* xn_s  = (float*)(smem + SM_XN);
    float* tau_s = (float*)(smem + SM_TAU);
    float* hm_s  = (float*)(smem + SM_HM);
    float* RVh   = (float*)(smem + SM_RVH);
    int*   RIh   = (int*)  (smem + SM_RIH);
    float* RV2h  = (float*)(smem + SM_RV2H);
    int*   besti_s = (int*)(smem + SM_BI);
    unsigned long long* res_s = (unsigned long long*)(smem + SM_RES);
    int*   items = (int*)  (smem + SM_ITM);
    int*   flg_s = (int*)  (smem + SM_FLG);
    int*   nit_p = (int*)  (smem + SM_CNT);
    float* RS    = (float*)(smem + SM_RS);

    const int tid = threadIdx.x;
    const int wid = tid >> 5, lid = tid & 31;
    const int l4  = lid & 3,  gq  = lid >> 2;
    const int colhalf = (wid >> 2) & 1;
    const int rq = wid & 3;
    const int r0 = rq*16 + gq, r1 = r0 + 8;

    // ---- tile-invariant setup ----
#pragma unroll
    for (int i = 0; i < 4; ++i) cn_s[tid + 256*i] = g_cnorm[tid + 256*i];
    const float nm  = sqrtf(__int_as_float(g_nm_i));
    const float nml = sqrtf(__int_as_float(g_nml_i));

    uint64_t srcbase; asm("cvta.to.global.u64 %0, %1;" : "=l"(srcbase)
                          : "l"(g_Bh16 + (size_t)(tid >> 3)*Dd + (tid & 7)*8));
    const uint32_t dstbase = sb + SM_B + (uint32_t)((tid >> 3)*BPITCH + (tid & 7)*16);

    for (;;){
        if (tid == 0) s_tile = atomicAdd(&g_tile, 1);
        __syncthreads();
        const int tile = s_tile;
        if (tile >= NTILES) break;
        const int row0 = tile * TR;
        if (tid == 0) *nit_p = 0;

        // ---- cp.async B chunk 0 -> buf0 ----
#pragma unroll
        for (int i = 0; i < 4; ++i)
            CP16(dstbase + (uint32_t)(i*32*BPITCH), srcbase + (uint64_t)(i*32*128));
        CP_COMMIT();

        // ---- X tile -> Xs ----
        {
            const float4* x4 = (const float4*)(x + (size_t)row0 * Dd);
#pragma unroll
            for (int i = 0; i < 4; ++i){
                int e = tid + 256*i;
                int r = e >> 4, g = e & 15;
                float4 v = x4[e];
                Xs[r*65 + g*4 + 0] = v.x; Xs[r*65 + g*4 + 1] = v.y;
                Xs[r*65 + g*4 + 2] = v.z; Xs[r*65 + g*4 + 3] = v.w;
            }
        }
        __syncthreads();

        // ---- per-row norms + rigorous tau ----
        if (tid < 64){
            float s = 0.f, sl = 0.f;
#pragma unroll
            for (int d = 0; d < 64; ++d){
                float v = Xs[tid*65 + d];
                float l = v - __half2float(__float2half_rn(v));
                s += v*v; sl += l*l;
            }
            xn_s[tid] = s;
            float xl = sqrtf(sl), xf = sqrtf(s);
            float tdot = xl*nm + (xf + xl)*nml;
            tau_s[tid] = 4.0f*tdot + 1e-3f;
        }

        // ---- A fragments: fp16 hi ----
        uint32_t Ah[16];
#pragma unroll
        for (int s = 0; s < 4; ++s){
#pragma unroll
            for (int p = 0; p < 2; ++p){
                int k0 = 16*s + 2*l4 + 8*p;
                __half2 hh;
                hh = __halves2half2(__float2half_rn(Xs[r0*65 + k0]),
                                    __float2half_rn(Xs[r0*65 + k0 + 1]));
                Ah[s*4 + p*2 + 0] = *(uint32_t*)&hh;
                hh = __halves2half2(__float2half_rn(Xs[r1*65 + k0]),
                                    __float2half_rn(Xs[r1*65 + k0 + 1]));
                Ah[s*4 + p*2 + 1] = *(uint32_t*)&hh;
            }
        }

        float bv0 = FLT_MAX, bv20 = FLT_MAX, bv1 = FLT_MAX, bv21 = FLT_MAX;
        int   bi0 = 0, bi1 = 0;

        // ---- chunk loop ----
        for (int c = 0; c < NCH; ++c){
            CP_WAIT(0);
            __syncthreads();
            if (c + 1 < NCH){
                const uint32_t dstb = dstbase + (uint32_t)(((c + 1) & 1) * SMB_BUFSZ);
                const uint64_t srcb = srcbase + (uint64_t)((c + 1) * 16384);
#pragma unroll
                for (int i = 0; i < 4; ++i)
                    CP16(dstb + (uint32_t)(i*32*BPITCH), srcb + (uint64_t)(i*32*128));
                CP_COMMIT();
            }

            const uint32_t bbase = sb + SM_B + (uint32_t)(c & 1) * SMB_BUFSZ
                                 + (uint32_t)((colhalf*64 + gq) * BPITCH + l4 * 32);
            float cmin0 = FLT_MAX, cmin1 = FLT_MAX;

            uint4 b0 = lds128(bbase);
            uint4 b1 = lds128(bbase + 16);
#pragma unroll
            for (int nt = 0; nt < 8; ++nt){
                uint4 nb0, nb1;
                if (nt < 7){
                    const uint32_t na = bbase + (uint32_t)((nt + 1) * 8 * BPITCH);
                    nb0 = lds128(na);
                    nb1 = lds128(na + 16);
                }

                // two independent accumulator chains, merged at the end
                float c0a=0.f,c1a=0.f,c2a=0.f,c3a=0.f;
                float c0b=0.f,c1b=0.f,c2b=0.f,c3b=0.f;
                MMA16(c0a,c1a,c2a,c3a, Ah[0], Ah[1], Ah[2], Ah[3],  b0.x, b0.y);
                MMA16(c0b,c1b,c2b,c3b, Ah[4], Ah[5], Ah[6], Ah[7],  b0.z, b0.w);
                MMA16(c0a,c1a,c2a,c3a, Ah[8], Ah[9], Ah[10],Ah[11], b1.x, b1.y);
                MMA16(c0b,c1b,c2b,c3b, Ah[12],Ah[13],Ah[14],Ah[15], b1.z, b1.w);
                float c0 = c0a + c0b;
                float c1 = c1a + c1b;
                float c2 = c2a + c2b;
                float c3 = c3a + c3b;

                const int colb = c*128 + colhalf*64 + nt*8 + l4*2;
                const float2 cn2 = *(const float2*)&cn_s[colb];
                float s0 = fmaf(-2.f, c0, cn2.x);
                float s1 = fmaf(-2.f, c1, cn2.y);
                float s2 = fmaf(-2.f, c2, cn2.x);
                float s3 = fmaf(-2.f, c3, cn2.y);

                // pair-min argmin update, exact top-2 maintenance
                {
                    float m = fminf(s0, s1), M = fmaxf(s0, s1);
                    int   i0 = (s1 < s0) ? (colb + 1) : colb;
                    float lose = fmaxf(bv0, m);
                    if (m < bv0){ bv0 = m; bi0 = i0; }
                    bv20 = fminf(bv20, fminf(lose, M));
                    cmin0 = fminf(cmin0, m);
                }
                {
                    float m = fminf(s2, s3), M = fmaxf(s2, s3);
                    int   i1 = (s3 < s2) ? (colb + 1) : colb;
                    float lose = fmaxf(bv1, m);
                    if (m < bv1){ bv1 = m; bi1 = i1; }
                    bv21 = fminf(bv21, fminf(lose, M));
                    cmin1 = fminf(cmin1, m);
                }

                b0 = nb0; b1 = nb1;
            }
            cmin0 = fminf(cmin0, __shfl_xor_sync(~0u, cmin0, 1));
            cmin0 = fminf(cmin0, __shfl_xor_sync(~0u, cmin0, 2));
            cmin1 = fminf(cmin1, __shfl_xor_sync(~0u, cmin1, 1));
            cmin1 = fminf(cmin1, __shfl_xor_sync(~0u, cmin1, 2));
            if (l4 == 0){
                hm_s[(colhalf*64 + r0)*8 + c] = cmin0;
                hm_s[(colhalf*64 + r1)*8 + c] = cmin1;
            }
        }

        // ---- quad-reduce best/second ----
#pragma unroll
        for (int off = 1; off < 4; off <<= 1){
            float ov  = __shfl_xor_sync(~0u, bv0, off);
            int   oi  = __shfl_xor_sync(~0u, bi0, off);
            float ov2 = __shfl_xor_sync(~0u, bv20, off);
            float lose;
            if (ov < bv0 || (ov == bv0 && oi < bi0)){ lose = bv0; bv0 = ov; bi0 = oi; }
            else lose = ov;
            bv20 = fminf(bv20, fminf(ov2, lose));

            ov  = __shfl_xor_sync(~0u, bv1, off);
            oi  = __shfl_xor_sync(~0u, bi1, off);
            ov2 = __shfl_xor_sync(~0u, bv21, off);
            if (ov < bv1 || (ov == bv1 && oi < bi1)){ lose = bv1; bv1 = ov; bi1 = oi; }
            else lose = ov;
            bv21 = fminf(bv21, fminf(ov2, lose));
        }
        if (l4 == 0){
            RVh [colhalf*64 + r0] = bv0;  RIh[colhalf*64 + r0] = bi0;  RV2h[colhalf*64 + r0] = bv20;
            RVh [colhalf*64 + r1] = bv1;  RIh[colhalf*64 + r1] = bi1;  RV2h[colhalf*64 + r1] = bv21;
        }
        __syncthreads();

        // ---- merge halves, flag, build (row,chunk) items ----
        if (tid < 64){
            float v0 = RVh[tid],  v1 = RVh[64+tid];
            int   i0 = RIh[tid],  i1 = RIh[64+tid];
            float s0 = RV2h[tid], s1 = RV2h[64+tid];
            float bv; int bi; float sec;
            if (v1 < v0 || (v1 == v0 && i1 < i0)){ bv = v1; bi = i1; sec = fminf(v0, s1); }
            else                                  { bv = v0; bi = i0; sec = fminf(v1, s0); }
            besti_s[tid] = bi;
            const float tau = tau_s[tid];
            int fl = (sec - bv < tau) ? 1 : 0;
            flg_s[tid] = fl;
            if (fl){
                res_s[tid] = ~0ull;
                const float lim = bv + tau;
#pragma unroll
                for (int c = 0; c < 8; ++c){
                    float cmn = fminf(hm_s[tid*8 + c], hm_s[(64+tid)*8 + c]);
                    if (cmn <= lim){
                        int s = atomicAdd(nit_p, 1);
                        items[s] = (tid << 3) | c;
                    }
                }
            }
        }
        __syncthreads();

        // ---- chunk-granular exact refine: warp per item ----
        const int nitems = *nit_p;
        for (int it = wid; it < nitems; it += 8){
            const int item = items[it];
            const int row = item >> 3, ch = item & 7;
            float a0 = 0.f, a1 = 0.f, a2 = 0.f, a3 = 0.f;
            const float4* bp = (const float4*)(cm + ch*128) + lid;
#pragma unroll 16
            for (int d = 0; d < 64; ++d){
                float4 b = __ldg(bp + d*256);
                float xv = Xs[row*65 + d];
                a0 = fmaf(xv, b.x, a0);
                a1 = fmaf(xv, b.y, a1);
                a2 = fmaf(xv, b.z, a2);
                a3 = fmaf(xv, b.w, a3);
            }
            const float xnr = xn_s[row];
            const int k0 = ch*128 + lid*4;
            float best = (xnr - 2.0f*a0) + cn_s[k0];     int bidx = k0;
            float sv;
            sv = (xnr - 2.0f*a1) + cn_s[k0+1]; if (sv < best){ best = sv; bidx = k0+1; }
            sv = (xnr - 2.0f*a2) + cn_s[k0+2]; if (sv < best){ best = sv; bidx = k0+2; }
            sv = (xnr - 2.0f*a3) + cn_s[k0+3]; if (sv < best){ best = sv; bidx = k0+3; }
#pragma unroll
            for (int off = 16; off > 0; off >>= 1){
                float ov = __shfl_xor_sync(~0u, best, off);
                int   oi = __shfl_xor_sync(~0u, bidx, off);
                if (ov < best || (ov == best && oi < bidx)){ best = ov; bidx = oi; }
            }
            if (lid == 0) atomicMin(&res_s[row], packsi(best, bidx));
        }
        __syncthreads();
        if (tid < 64 && flg_s[tid])
            besti_s[tid] = (int)(res_s[tid] & 0x3FFull);
        __syncthreads();

        // ---- gather + STE output + loss ----
        float partial = 0.f;
        {
            const int row = tid >> 2, q = tid & 3;
            const int bi = besti_s[row];
            if (q == 0) out_idx[row0 + row] = (float)bi;
            const float4* q4 = (const float4*)(g_codebookT + (size_t)bi * Dd) + q*4;
            float4* o4 = (float4*)(out + (size_t)(row0 + row) * Dd) + q*4;
#pragma unroll
            for (int g = 0; g < 4; ++g){
                float4 qv = q4[g];
                int db = q*16 + g*4;
                float xa = Xs[row*65 + db + 0];
                float xb = Xs[row*65 + db + 1];
                float xc = Xs[row*65 + db + 2];
                float xd = Xs[row*65 + db + 3];
                float da = qv.x - xa, dbv = qv.y - xb, dc = qv.z - xc, dd = qv.w - xd;
                partial += da*da + dbv*dbv + dc*dc + dd*dd;
                float4 o; o.x = xa + da; o.y = xb + dbv; o.z = xc + dc; o.w = xd + dd;
                o4[g] = o;
            }
        }
        RS[tid] = partial;
        __syncthreads();
        for (int s = 128; s > 0; s >>= 1){
            if (tid < s) RS[tid] += RS[tid + s];
            __syncthreads();
        }
        if (tid == 0) g_blocksum[tile] = RS[0];
    }

    // ---- fused finish: last CTA does deterministic fp64 loss sum ----
    __threadfence();
    if (tid == 0) s_done = atomicAdd(&g_done, 1);
    __syncthreads();
    if (s_done == (int)gridDim.x - 1){
        __shared__ double part[32];
        if (tid < 32){
            double s = 0.0;
            const int per = NTILES / 32;
            for (int i = 0; i < per; ++i) s += (double)g_blocksum[tid*per + i];
            part[tid] = s;
        }
        __syncthreads();
        if (tid == 0){
            double tot = 0.0;
            for (int i = 0; i < 32; ++i) tot += part[i];
            float q_loss = (float)(tot / (double)(65536.0 * 64.0));
            out_loss[0] = q_loss + 0.25f * q_loss;
        }
    }
}

// ---------------------------------------------------------------------------
extern "C" void kernel_launch(void* const* d_in, const int* in_sizes, int n_in,
                              void* d_out, int out_size) {
    const float* x  = (const float*)d_in[0];
    const float* cm = (const float*)d_in[1];
    float* out = (float*)d_out;

    const int N = in_sizes[0] / Dd;            // 65536
    float* out_idx  = out + (size_t)N * Dd;
    float* out_loss = out_idx + N;

    cudaFuncSetAttribute(vq_main, cudaFuncAttributeMaxDynamicSharedMemorySize, SM_TOTAL);

    vq_prep<<<Kk/8, 128>>>(cm);
    vq_main<<<GRID, 256, SM_TOTAL>>>(x, cm, out, out_idx, out_loss);
}

// round 12
// speedup vs baseline: 1.0190x; 1.0109x over previous
#include <cuda_runtime.h>
#include <cuda_fp16.h>
#include <cstdint>
#include <cfloat>

#define Dd 64
#define Kk 1024
#define TR 64
#define NCH 8
#define NTILES 1024
#define GRID 296

#define BPITCH 144
#define SMB_BUFSZ (128*BPITCH)

// ---------------- smem layout (bytes) ----------------
#define SM_B    0                  // 2 x 18432 = 36864
#define SM_XS   36864              // 64 x 65 fp32 -> 53504
#define SM_CN   53504              // -> 57600
#define SM_XN   57600              // -> 57856
#define SM_TAU  57856              // -> 58112
#define SM_HM   58112              // [4 cq][64 rows][8] f32 = 8192 -> 66304
#define SM_RVH  66304              // [4][64] f32 -> 67328
#define SM_RIH  67328              // -> 68352
#define SM_RV2H 68352              // -> 69376
#define SM_BI   69376              // 64 int -> 69632
#define SM_RES  69632              // 64 u64 -> 70144
#define SM_ITM  70144              // 512 int -> 72192
#define SM_FLG  72192              // -> 72448
#define SM_CNT  72448              // 8
#define SM_RS   72456              // 256 f32 -> 73480
#define SM_TOTAL 73480

// ---------------- scratch ----------------
__device__ float  g_codebookT[Kk*Dd];
__device__ float  g_cnorm[Kk];
__device__ __half g_Bh16[Kk*Dd];
__device__ int    g_nm_i;
__device__ int    g_nml_i;
__device__ float  g_blocksum[NTILES];
__device__ int    g_done;
__device__ int    g_tile;

// ---------------- helpers ----------------
__device__ __forceinline__ uint32_t smem_u32(const void* p){
    uint32_t a; asm("{ .reg .u64 t; cvta.to.shared.u64 t, %1; cvt.u32.u64 %0, t; }" : "=r"(a) : "l"(p)); return a;
}
__device__ __forceinline__ uint4 lds128(uint32_t a){
    uint4 v; asm volatile("ld.shared.v4.u32 {%0,%1,%2,%3}, [%4];"
        : "=r"(v.x),"=r"(v.y),"=r"(v.z),"=r"(v.w) : "r"(a)); return v;
}
#define CP16(dst, src) asm volatile("cp.async.cg.shared.global [%0], [%1], 16;" :: "r"(dst), "l"(src) : "memory")
#define CP_COMMIT()    asm volatile("cp.async.commit_group;" ::: "memory")
#define CP_WAIT(n)     asm volatile("cp.async.wait_group %0;" :: "n"(n) : "memory")

#define MMA16(c0,c1,c2,c3, a0,a1,a2,a3, b0,b1) \
  asm volatile("mma.sync.aligned.m16n8k16.row.col.f32.f16.f16.f32 " \
    "{%0,%1,%2,%3},{%4,%5,%6,%7},{%8,%9},{%0,%1,%2,%3};" \
    : "+f"(c0),"+f"(c1),"+f"(c2),"+f"(c3) \
    : "r"(a0),"r"(a1),"r"(a2),"r"(a3),"r"(b0),"r"(b1))

// pair-min argmin update with exact top-2 maintenance
#define PAIRUPD(BV,BI,BV2,CM, sa, sb, col) do{ \
    float _m = fminf((sa),(sb)), _M = fmaxf((sa),(sb)); \
    int _i = ((sb) < (sa)) ? ((col)+1) : (col); \
    float _lose = fmaxf(BV, _m); \
    if (_m < BV){ BV = _m; BI = _i; } \
    BV2 = fminf(BV2, fminf(_lose, _M)); \
    CM = fminf(CM, _m); \
}while(0)

__device__ __forceinline__ int bslot(int d){
    int s = d >> 4, r = d & 15;
    return ((r >> 1) & 3) * 16 + s * 4 + ((r >> 3) & 1) * 2 + (r & 1);
}

__device__ __forceinline__ unsigned long long packsi(float s, int idx){
    uint32_t u = __float_as_uint(s);
    u = (u >> 31) ? ~u : (u | 0x80000000u);
    return ((unsigned long long)u << 10) | (uint32_t)idx;
}

// ---------------------------------------------------------------------------
// Prep: transpose, fp16 hi split (permuted), norms; resets work-queue/done.
// ---------------------------------------------------------------------------
__global__ void vq_prep(const float* __restrict__ cm){
    __shared__ float tile[64][9];
    __shared__ float mx_s[8], mxl_s[8];
    const int t  = threadIdx.x;          // 128 threads
    const int kb = blockIdx.x * 8;
    if (blockIdx.x == 0 && t == 0){ g_done = 0; g_tile = 0; }
#pragma unroll
    for (int i = 0; i < 4; ++i){
        int e = t + 128*i;
        int d = e >> 3, j = e & 7;
        tile[d][j] = cm[d*Kk + kb + j];
    }
    __syncthreads();
#pragma unroll
    for (int i = 0; i < 4; ++i){
        int e = t + 128*i;
        int kr = e >> 6, jd = e & 63;
        float v = tile[jd][kr];
        g_codebookT[(kb + kr)*Dd + jd] = v;
        g_Bh16[(kb + kr)*Dd + bslot(jd)] = __float2half_rn(v);
    }
    if (t < 8){
        float s = 0.f, sl = 0.f;
#pragma unroll
        for (int d = 0; d < 64; ++d){
            float v = tile[d][t];
            float l = v - __half2float(__float2half_rn(v));
            s += v*v; sl += l*l;
        }
        g_cnorm[kb + t] = s;
        mx_s[t] = s; mxl_s[t] = sl;
    }
    __syncthreads();
    if (t == 0){
        float m = mx_s[0], ml = mxl_s[0];
#pragma unroll
        for (int i = 1; i < 8; ++i){ m = fmaxf(m, mx_s[i]); ml = fmaxf(ml, mxl_s[i]); }
        atomicMax(&g_nm_i,  __float_as_int(m));
        atomicMax(&g_nml_i, __float_as_int(ml));
    }
}

// ---------------------------------------------------------------------------
// Main: persistent CTAs; warp = 32 rows x 32 cols (8 MMA per B fragment);
// rigorous tau; chunk-granular exact refine; gather/STE/loss; fused finish.
// ---------------------------------------------------------------------------
__global__ __launch_bounds__(256, 2)
void vq_main(const float* __restrict__ x, const float* __restrict__ cm,
             float* __restrict__ out, float* __restrict__ out_idx,
             float* __restrict__ out_loss)
{
    extern __shared__ char smem[];
    __shared__ int s_tile;
    __shared__ int s_done;
    const uint32_t sb = smem_u32(smem);
    float* Xs    = (float*)(smem + SM_XS);
    float* cn_s  = (float*)(smem + SM_CN);
    float* xn_s  = (float*)(smem + SM_XN);
    float* tau_s = (float*)(smem + SM_TAU);
    float* hm_s  = (float*)(smem + SM_HM);
    float* RVh   = (float*)(smem + SM_RVH);
    int*   RIh   = (int*)  (smem + SM_RIH);
    float* RV2h  = (float*)(smem + SM_RV2H);
    int*   besti_s = (int*)(smem + SM_BI);
    unsigned long long* res_s = (unsigned long long*)(smem + SM_RES);
    int*   items = (int*)  (smem + SM_ITM);
    int*   flg_s = (int*)  (smem + SM_FLG);
    int*   nit_p = (int*)  (smem + SM_CNT);
    float* RS    = (float*)(smem + SM_RS);

    const int tid = threadIdx.x;
    const int wid = tid >> 5, lid = tid & 31;
    const int l4  = lid & 3,  gq  = lid >> 2;
    const int rh  = wid >> 2;            // row half: 0/1 (32 rows)
    const int cq  = wid & 3;             // col quad: 0..3 (32 cols)
    const int rk0 = rh*32 + gq;          // tracked rows for this lane
    const int rk1 = rk0 + 8, rk2 = rk0 + 16, rk3 = rk0 + 24;

    // ---- tile-invariant setup ----
#pragma unroll
    for (int i = 0; i < 4; ++i) cn_s[tid + 256*i] = g_cnorm[tid + 256*i];
    const float nm  = sqrtf(__int_as_float(g_nm_i));
    const float nml = sqrtf(__int_as_float(g_nml_i));

    uint64_t srcbase; asm("cvta.to.global.u64 %0, %1;" : "=l"(srcbase)
                          : "l"(g_Bh16 + (size_t)(tid >> 3)*Dd + (tid & 7)*8));
    const uint32_t dstbase = sb + SM_B + (uint32_t)((tid >> 3)*BPITCH + (tid & 7)*16);

    for (;;){
        if (tid == 0) s_tile = atomicAdd(&g_tile, 1);
        __syncthreads();
        const int tile = s_tile;
        if (tile >= NTILES) break;
        const int row0 = tile * TR;
        if (tid == 0) *nit_p = 0;

        // ---- cp.async B chunk 0 -> buf0 ----
#pragma unroll
        for (int i = 0; i < 4; ++i)
            CP16(dstbase + (uint32_t)(i*32*BPITCH), srcbase + (uint64_t)(i*32*128));
        CP_COMMIT();

        // ---- X tile -> Xs ----
        {
            const float4* x4 = (const float4*)(x + (size_t)row0 * Dd);
#pragma unroll
            for (int i = 0; i < 4; ++i){
                int e = tid + 256*i;
                int r = e >> 4, g = e & 15;
                float4 v = x4[e];
                Xs[r*65 + g*4 + 0] = v.x; Xs[r*65 + g*4 + 1] = v.y;
                Xs[r*65 + g*4 + 2] = v.z; Xs[r*65 + g*4 + 3] = v.w;
            }
        }
        __syncthreads();

        // ---- per-row norms + rigorous tau ----
        if (tid < 64){
            float s = 0.f, sl = 0.f;
#pragma unroll
            for (int d = 0; d < 64; ++d){
                float v = Xs[tid*65 + d];
                float l = v - __half2float(__float2half_rn(v));
                s += v*v; sl += l*l;
            }
            xn_s[tid] = s;
            float xl = sqrtf(sl), xf = sqrtf(s);
            float tdot = xl*nm + (xf + xl)*nml;
            tau_s[tid] = 4.0f*tdot + 1e-3f;
        }

        // ---- A fragments: fp16 hi, 32 rows (2 MMA row-groups) ----
        uint32_t Ah[32];
#pragma unroll
        for (int g = 0; g < 2; ++g){
            const int ra = rh*32 + g*16 + gq, rb = ra + 8;
#pragma unroll
            for (int s = 0; s < 4; ++s){
#pragma unroll
                for (int p = 0; p < 2; ++p){
                    int k0 = 16*s + 2*l4 + 8*p;
                    __half2 hh;
                    hh = __halves2half2(__float2half_rn(Xs[ra*65 + k0]),
                                        __float2half_rn(Xs[ra*65 + k0 + 1]));
                    Ah[g*16 + s*4 + p*2 + 0] = *(uint32_t*)&hh;
                    hh = __halves2half2(__float2half_rn(Xs[rb*65 + k0]),
                                        __float2half_rn(Xs[rb*65 + k0 + 1]));
                    Ah[g*16 + s*4 + p*2 + 1] = *(uint32_t*)&hh;
                }
            }
        }

        float bv0 = FLT_MAX, bv1 = FLT_MAX, bv2 = FLT_MAX, bv3 = FLT_MAX;
        float sv0 = FLT_MAX, sv1 = FLT_MAX, sv2 = FLT_MAX, sv3 = FLT_MAX;
        int   bi0 = 0, bi1 = 0, bi2 = 0, bi3 = 0;

        // ---- chunk loop ----
        for (int c = 0; c < NCH; ++c){
            CP_WAIT(0);
            __syncthreads();
            if (c + 1 < NCH){
                const uint32_t dstb = dstbase + (uint32_t)(((c + 1) & 1) * SMB_BUFSZ);
                const uint64_t srcb = srcbase + (uint64_t)((c + 1) * 16384);
#pragma unroll
                for (int i = 0; i < 4; ++i)
                    CP16(dstb + (uint32_t)(i*32*BPITCH), srcb + (uint64_t)(i*32*128));
                CP_COMMIT();
            }

            const uint32_t bbase = sb + SM_B + (uint32_t)(c & 1) * SMB_BUFSZ
                                 + (uint32_t)((cq*32 + gq) * BPITCH + l4 * 32);
            float cm0 = FLT_MAX, cm1 = FLT_MAX, cm2 = FLT_MAX, cm3 = FLT_MAX;
#pragma unroll
            for (int nt = 0; nt < 4; ++nt){
                const uint32_t nb = bbase + (uint32_t)(nt * 8 * BPITCH);
                uint4 b0 = lds128(nb);
                uint4 b1 = lds128(nb + 16);

                // row-group 0 (rows rh*32+0..15): two split chains
                float cA0=0,cA1=0,cA2=0,cA3=0, cB0=0,cB1=0,cB2=0,cB3=0;
                MMA16(cA0,cA1,cA2,cA3, Ah[0], Ah[1], Ah[2], Ah[3],  b0.x, b0.y);
                MMA16(cB0,cB1,cB2,cB3, Ah[4], Ah[5], Ah[6], Ah[7],  b0.z, b0.w);
                MMA16(cA0,cA1,cA2,cA3, Ah[8], Ah[9], Ah[10],Ah[11], b1.x, b1.y);
                MMA16(cB0,cB1,cB2,cB3, Ah[12],Ah[13],Ah[14],Ah[15], b1.z, b1.w);
                // row-group 1 (rows rh*32+16..31)
                float dA0=0,dA1=0,dA2=0,dA3=0, dB0=0,dB1=0,dB2=0,dB3=0;
                MMA16(dA0,dA1,dA2,dA3, Ah[16],Ah[17],Ah[18],Ah[19], b0.x, b0.y);
                MMA16(dB0,dB1,dB2,dB3, Ah[20],Ah[21],Ah[22],Ah[23], b0.z, b0.w);
                MMA16(dA0,dA1,dA2,dA3, Ah[24],Ah[25],Ah[26],Ah[27], b1.x, b1.y);
                MMA16(dB0,dB1,dB2,dB3, Ah[28],Ah[29],Ah[30],Ah[31], b1.z, b1.w);

                float c0 = cA0 + cB0, c1 = cA1 + cB1, c2 = cA2 + cB2, c3 = cA3 + cB3;
                float d0 = dA0 + dB0, d1 = dA1 + dB1, d2 = dA2 + dB2, d3 = dA3 + dB3;

                const int colb = c*128 + cq*32 + nt*8 + l4*2;
                const float2 cn2 = *(const float2*)&cn_s[colb];
                float s0 = fmaf(-2.f, c0, cn2.x);
                float s1 = fmaf(-2.f, c1, cn2.y);
                float s2 = fmaf(-2.f, c2, cn2.x);
                float s3 = fmaf(-2.f, c3, cn2.y);
                float s4 = fmaf(-2.f, d0, cn2.x);
                float s5 = fmaf(-2.f, d1, cn2.y);
                float s6 = fmaf(-2.f, d2, cn2.x);
                float s7 = fmaf(-2.f, d3, cn2.y);

                PAIRUPD(bv0, bi0, sv0, cm0, s0, s1, colb);   // row rk0
                PAIRUPD(bv1, bi1, sv1, cm1, s2, s3, colb);   // row rk1
                PAIRUPD(bv2, bi2, sv2, cm2, s4, s5, colb);   // row rk2
                PAIRUPD(bv3, bi3, sv3, cm3, s6, s7, colb);   // row rk3
            }
            cm0 = fminf(cm0, __shfl_xor_sync(~0u, cm0, 1));
            cm0 = fminf(cm0, __shfl_xor_sync(~0u, cm0, 2));
            cm1 = fminf(cm1, __shfl_xor_sync(~0u, cm1, 1));
            cm1 = fminf(cm1, __shfl_xor_sync(~0u, cm1, 2));
            cm2 = fminf(cm2, __shfl_xor_sync(~0u, cm2, 1));
            cm2 = fminf(cm2, __shfl_xor_sync(~0u, cm2, 2));
            cm3 = fminf(cm3, __shfl_xor_sync(~0u, cm3, 1));
            cm3 = fminf(cm3, __shfl_xor_sync(~0u, cm3, 2));
            if (l4 == 0){
                hm_s[(cq*64 + rk0)*8 + c] = cm0;
                hm_s[(cq*64 + rk1)*8 + c] = cm1;
                hm_s[(cq*64 + rk2)*8 + c] = cm2;
                hm_s[(cq*64 + rk3)*8 + c] = cm3;
            }
        }

        // ---- quad-reduce best/second over the 4 l4 lanes ----
#pragma unroll
        for (int off = 1; off < 4; off <<= 1){
#define QRED(BV,BI,SV) { \
            float _ov  = __shfl_xor_sync(~0u, BV, off); \
            int   _oi  = __shfl_xor_sync(~0u, BI, off); \
            float _ov2 = __shfl_xor_sync(~0u, SV, off); \
            float _lose; \
            if (_ov < BV || (_ov == BV && _oi < BI)){ _lose = BV; BV = _ov; BI = _oi; } \
            else _lose = _ov; \
            SV = fminf(SV, fminf(_ov2, _lose)); }
            QRED(bv0, bi0, sv0)
            QRED(bv1, bi1, sv1)
            QRED(bv2, bi2, sv2)
            QRED(bv3, bi3, sv3)
#undef QRED
        }
        if (l4 == 0){
            RVh[cq*64 + rk0] = bv0; RIh[cq*64 + rk0] = bi0; RV2h[cq*64 + rk0] = sv0;
            RVh[cq*64 + rk1] = bv1; RIh[cq*64 + rk1] = bi1; RV2h[cq*64 + rk1] = sv1;
            RVh[cq*64 + rk2] = bv2; RIh[cq*64 + rk2] = bi2; RV2h[cq*64 + rk2] = sv2;
            RVh[cq*64 + rk3] = bv3; RIh[cq*64 + rk3] = bi3; RV2h[cq*64 + rk3] = sv3;
        }
        __syncthreads();

        // ---- merge col-quads, flag, build (row,chunk) items ----
        if (tid < 64){
            float bv = RVh[tid]; int bi = RIh[tid]; float sec = RV2h[tid];
#pragma unroll
            for (int q = 1; q < 4; ++q){
                float v  = RVh[q*64 + tid];
                int   iv = RIh[q*64 + tid];
                float s2 = RV2h[q*64 + tid];
                if (v < bv || (v == bv && iv < bi)){ sec = fminf(s2, bv); bv = v; bi = iv; }
                else sec = fminf(sec, v);
            }
            besti_s[tid] = bi;
            const float tau = tau_s[tid];
            int fl = (sec - bv < tau) ? 1 : 0;
            flg_s[tid] = fl;
            if (fl){
                res_s[tid] = ~0ull;
                const float lim = bv + tau;
#pragma unroll
                for (int c = 0; c < 8; ++c){
                    float cmn = fminf(fminf(hm_s[tid*8 + c],        hm_s[(64+tid)*8 + c]),
                                      fminf(hm_s[(128+tid)*8 + c],  hm_s[(192+tid)*8 + c]));
                    if (cmn <= lim){
                        int s = atomicAdd(nit_p, 1);
                        items[s] = (tid << 3) | c;
                    }
                }
            }
        }
        __syncthreads();

        // ---- chunk-granular exact refine: warp per item ----
        const int nitems = *nit_p;
        for (int it = wid; it < nitems; it += 8){
            const int item = items[it];
            const int row = item >> 3, ch = item & 7;
            float a0 = 0.f, a1 = 0.f, a2 = 0.f, a3 = 0.f;
            const float4* bp = (const float4*)(cm + ch*128) + lid;
#pragma unroll 16
            for (int d = 0; d < 64; ++d){
                float4 b = __ldg(bp + d*256);
                float xv = Xs[row*65 + d];
                a0 = fmaf(xv, b.x, a0);
                a1 = fmaf(xv, b.y, a1);
                a2 = fmaf(xv, b.z, a2);
                a3 = fmaf(xv, b.w, a3);
            }
            const float xnr = xn_s[row];
            const int k0 = ch*128 + lid*4;
            float best = (xnr - 2.0f*a0) + cn_s[k0];     int bidx = k0;
            float sv;
            sv = (xnr - 2.0f*a1) + cn_s[k0+1]; if (sv < best){ best = sv; bidx = k0+1; }
            sv = (xnr - 2.0f*a2) + cn_s[k0+2]; if (sv < best){ best = sv; bidx = k0+2; }
            sv = (xnr - 2.0f*a3) + cn_s[k0+3]; if (sv < best){ best = sv; bidx = k0+3; }
#pragma unroll
            for (int off = 16; off > 0; off >>= 1){
                float ov = __shfl_xor_sync(~0u, best, off);
                int   oi = __shfl_xor_sync(~0u, bidx, off);
                if (ov < best || (ov == best && oi < bidx)){ best = ov; bidx = oi; }
            }
            if (lid == 0) atomicMin(&res_s[row], packsi(best, bidx));
        }
        __syncthreads();
        if (tid < 64 && flg_s[tid])
            besti_s[tid] = (int)(res_s[tid] & 0x3FFull);
        __syncthreads();

        // ---- gather + STE output + loss ----
        float partial = 0.f;
        {
            const int row = tid >> 2, q = tid & 3;
            const int bi = besti_s[row];
            if (q == 0) out_idx[row0 + row] = (float)bi;
            const float4* q4 = (const float4*)(g_codebookT + (size_t)bi * Dd) + q*4;
            float4* o4 = (float4*)(out + (size_t)(row0 + row) * Dd) + q*4;
#pragma unroll
            for (int g = 0; g < 4; ++g){
                float4 qv = q4[g];
                int db = q*16 + g*4;
                float xa = Xs[row*65 + db + 0];
                float xb = Xs[row*65 + db + 1];
                float xc = Xs[row*65 + db + 2];
                float xd = Xs[row*65 + db + 3];
                float da = qv.x - xa, dbv = qv.y - xb, dc = qv.z - xc, dd = qv.w - xd;
                partial += da*da + dbv*dbv + dc*dc + dd*dd;
                float4 o; o.x = xa + da; o.y = xb + dbv; o.z = xc + dc; o.w = xd + dd;
                o4[g] = o;
            }
        }
        RS[tid] = partial;
        __syncthreads();
        for (int s = 128; s > 0; s >>= 1){
            if (tid < s) RS[tid] += RS[tid + s];
            __syncthreads();
        }
        if (tid == 0) g_blocksum[tile] = RS[0];
    }

    // ---- fused finish: last CTA does deterministic fp64 loss sum ----
    __threadfence();
    if (tid == 0) s_done = atomicAdd(&g_done, 1);
    __syncthreads();
    if (s_done == (int)gridDim.x - 1){
        __shared__ double part[32];
        if (tid < 32){
            double s = 0.0;
            const int per = NTILES / 32;
            for (int i = 0; i < per; ++i) s += (double)g_blocksum[tid*per + i];
            part[tid] = s;
        }
        __syncthreads();
        if (tid == 0){
            double tot = 0.0;
            for (int i = 0; i < 32; ++i) tot += part[i];
            float q_loss = (float)(tot / (double)(65536.0 * 64.0));
            out_loss[0] = q_loss + 0.25f * q_loss;
        }
    }
}

// ---------------------------------------------------------------------------
extern "C" void kernel_launch(void* const* d_in, const int* in_sizes, int n_in,
                              void* d_out, int out_size) {
    const float* x  = (const float*)d_in[0];
    const float* cm = (const float*)d_in[1];
    float* out = (float*)d_out;

    const int N = in_sizes[0] / Dd;            // 65536
    float* out_idx  = out + (size_t)N * Dd;
    float* out_loss = out_idx + N;

    cudaFuncSetAttribute(vq_main, cudaFuncAttributeMaxDynamicSharedMemorySize, SM_TOTAL);

    vq_prep<<<Kk/8, 128>>>(cm);
    vq_main<<<GRID, 256, SM_TOTAL>>>(x, cm, out, out_idx, out_loss);
}